// round 2
// baseline (speedup 1.0000x reference)
#include <cuda_runtime.h>

#define NN 100000
#define DD 128
#define EE 1600000

// ---------------- scratch (no allocations allowed) ----------------
__device__ __align__(16) float g_bufA[NN * DD];
__device__ __align__(16) float g_bufB[NN * DD];
__device__ __align__(16) float g_agg [NN * DD];

// ---------------- zero agg ----------------
__global__ void zero_kernel(float4* __restrict__ p) {
    int i = blockIdx.x * blockDim.x + threadIdx.x;
    p[i] = make_float4(0.f, 0.f, 0.f, 0.f);
}

// ---------------- edge scatter: one warp per edge, float4 per lane ----------------
__global__ void scatter_kernel(const float* __restrict__ h,
                               const int* __restrict__ src,
                               const int* __restrict__ dst,
                               float* __restrict__ agg) {
    int gid  = blockIdx.x * blockDim.x + threadIdx.x;
    int e    = gid >> 5;
    int lane = gid & 31;
    if (e >= EE) return;
    int s = __ldg(src + e);
    int d = __ldg(dst + e);
    float4 v = __ldg(reinterpret_cast<const float4*>(h + (size_t)s * DD) + lane);
    float* p = agg + (size_t)d * DD + (lane << 2);
    asm volatile("red.global.add.v4.f32 [%0], {%1,%2,%3,%4};"
                 :: "l"(p), "f"(v.x), "f"(v.y), "f"(v.z), "f"(v.w)
                 : "memory");
}

// ---------------- fused GEMM:  out = agg@Wrel + b + h@Wroot  (+epilogue) ----------------
// MODE 0: relu -> LN                 (input layer)
// MODE 1: +h residual -> relu -> LN  (middle layers)
// MODE 2: plain                      (output layer)
//
// Block tile 128 rows x 128 cols, K = 256 ([agg | h] concat), 256 threads,
// 8x8 register micro-tile with split-column mapping (tx*4 and 64+tx*4) for
// conflict-free LDS.128.
template <int MODE>
__global__ void __launch_bounds__(256, 2)
gemm_kernel(const float* __restrict__ agg,  const float* __restrict__ hin,
            const float* __restrict__ Wrel, const float* __restrict__ Wroot,
            const float* __restrict__ bias, const float* __restrict__ gamma,
            const float* __restrict__ beta, float* __restrict__ outp) {
    __shared__ float As[16][128];
    __shared__ float Ws[16][128];

    const int tid     = threadIdx.x;
    const int tx      = tid & 15;
    const int ty      = tid >> 4;
    const int rowBase = blockIdx.x * 128;

    float acc[8][8];
#pragma unroll
    for (int i = 0; i < 8; i++)
#pragma unroll
        for (int j = 0; j < 8; j++) acc[i][j] = 0.f;

    for (int kt = 0; kt < 16; kt++) {
        const int kk0 = kt * 16;
        // ---- stage A chunk (transposed): As[k][row] ----
#pragma unroll
        for (int r = 0; r < 2; r++) {
            int f4   = tid + r * 256;
            int row  = f4 >> 2;      // 0..127
            int kq   = f4 & 3;       // 0..3 (float4 index along k)
            int grow = rowBase + row;
            int kk   = kk0 + kq * 4;
            float4 v = make_float4(0.f, 0.f, 0.f, 0.f);
            if (grow < NN) {
                const float* b = (kk < DD)
                    ? (agg + (size_t)grow * DD + kk)
                    : (hin + (size_t)grow * DD + (kk - DD));
                v = *reinterpret_cast<const float4*>(b);
            }
            As[kq * 4 + 0][row] = v.x;
            As[kq * 4 + 1][row] = v.y;
            As[kq * 4 + 2][row] = v.z;
            As[kq * 4 + 3][row] = v.w;
        }
        // ---- stage W chunk: Ws[k][n] ----
#pragma unroll
        for (int r = 0; r < 2; r++) {
            int f4 = tid + r * 256;
            int k  = f4 >> 5;        // 0..15
            int nq = f4 & 31;        // 0..31
            int kk = kk0 + k;
            const float* b = (kk < DD)
                ? (Wrel  + (size_t)kk * DD + nq * 4)
                : (Wroot + (size_t)(kk - DD) * DD + nq * 4);
            *reinterpret_cast<float4*>(&Ws[k][nq * 4]) =
                *reinterpret_cast<const float4*>(b);
        }
        __syncthreads();
#pragma unroll
        for (int k = 0; k < 16; k++) {
            float a[8], w[8];
            *reinterpret_cast<float4*>(&a[0]) = *reinterpret_cast<const float4*>(&As[k][ty * 4]);
            *reinterpret_cast<float4*>(&a[4]) = *reinterpret_cast<const float4*>(&As[k][64 + ty * 4]);
            *reinterpret_cast<float4*>(&w[0]) = *reinterpret_cast<const float4*>(&Ws[k][tx * 4]);
            *reinterpret_cast<float4*>(&w[4]) = *reinterpret_cast<const float4*>(&Ws[k][64 + tx * 4]);
#pragma unroll
            for (int i = 0; i < 8; i++)
#pragma unroll
                for (int j = 0; j < 8; j++)
                    acc[i][j] += a[i] * w[j];
        }
        __syncthreads();
    }

    // ---- fused epilogue ----
    float bb[8], gg[8], be[8];
    *reinterpret_cast<float4*>(&bb[0]) = *reinterpret_cast<const float4*>(bias + tx * 4);
    *reinterpret_cast<float4*>(&bb[4]) = *reinterpret_cast<const float4*>(bias + 64 + tx * 4);
    if (MODE != 2) {
        *reinterpret_cast<float4*>(&gg[0]) = *reinterpret_cast<const float4*>(gamma + tx * 4);
        *reinterpret_cast<float4*>(&gg[4]) = *reinterpret_cast<const float4*>(gamma + 64 + tx * 4);
        *reinterpret_cast<float4*>(&be[0]) = *reinterpret_cast<const float4*>(beta + tx * 4);
        *reinterpret_cast<float4*>(&be[4]) = *reinterpret_cast<const float4*>(beta + 64 + tx * 4);
    }

#pragma unroll
    for (int i = 0; i < 8; i++) {
        int  m     = rowBase + ((i < 4) ? (ty * 4 + i) : (64 + ty * 4 + (i - 4)));
        bool valid = (m < NN);
        float v[8];
        float res[8];
        if (MODE == 1) {
            if (valid) {
                *reinterpret_cast<float4*>(&res[0]) =
                    *reinterpret_cast<const float4*>(hin + (size_t)m * DD + tx * 4);
                *reinterpret_cast<float4*>(&res[4]) =
                    *reinterpret_cast<const float4*>(hin + (size_t)m * DD + 64 + tx * 4);
            } else {
#pragma unroll
                for (int j = 0; j < 8; j++) res[j] = 0.f;
            }
        }
#pragma unroll
        for (int j = 0; j < 8; j++) {
            float t = acc[i][j] + bb[j];
            if (MODE == 1) t += res[j];
            if (MODE != 2) t = fmaxf(t, 0.f);
            v[j] = t;
        }
        if (MODE == 2) {
            if (valid) {
                *reinterpret_cast<float4*>(outp + (size_t)m * DD + tx * 4) =
                    *reinterpret_cast<const float4*>(&v[0]);
                *reinterpret_cast<float4*>(outp + (size_t)m * DD + 64 + tx * 4) =
                    *reinterpret_cast<const float4*>(&v[4]);
            }
            continue;
        }
        // LayerNorm over the 128 cols of row m: 16-lane (same half-warp) reduction.
        float s = 0.f, q = 0.f;
#pragma unroll
        for (int j = 0; j < 8; j++) { s += v[j]; q += v[j] * v[j]; }
#pragma unroll
        for (int o = 1; o < 16; o <<= 1) {
            s += __shfl_xor_sync(0xffffffffu, s, o);
            q += __shfl_xor_sync(0xffffffffu, q, o);
        }
        float mean = s * (1.f / 128.f);
        float var  = q * (1.f / 128.f) - mean * mean;
        float rstd = rsqrtf(var + 1e-5f);
#pragma unroll
        for (int j = 0; j < 8; j++)
            v[j] = (v[j] - mean) * rstd * gg[j] + be[j];
        if (valid) {
            *reinterpret_cast<float4*>(outp + (size_t)m * DD + tx * 4) =
                *reinterpret_cast<const float4*>(&v[0]);
            *reinterpret_cast<float4*>(outp + (size_t)m * DD + 64 + tx * 4) =
                *reinterpret_cast<const float4*>(&v[4]);
        }
    }
}

// ---------------- driver ----------------
extern "C" void kernel_launch(void* const* d_in, const int* in_sizes, int n_in,
                              void* d_out, int out_size) {
    const float* in_feat = (const float*)d_in[0];
    const int*   ei      = (const int*)  d_in[1];   // [2, E]: src then dst
    const float* W_rel   = (const float*)d_in[2];   // [4, 128, 128]
    const float* b_rel   = (const float*)d_in[3];   // [4, 128]
    const float* W_root  = (const float*)d_in[4];   // [4, 128, 128]
    const float* gamma   = (const float*)d_in[5];
    const float* beta    = (const float*)d_in[6];
    float*       out     = (float*)d_out;

    float *pA = nullptr, *pB = nullptr, *pAgg = nullptr;
    cudaGetSymbolAddress((void**)&pA,   g_bufA);
    cudaGetSymbolAddress((void**)&pB,   g_bufB);
    cudaGetSymbolAddress((void**)&pAgg, g_agg);

    const int* src = ei;
    const int* dst = ei + EE;

    const int ZERO_BLOCKS    = (NN * DD / 4) / 256;       // 12500
    const int SCATTER_BLOCKS = (EE * 32) / 256;           // 200000
    const int GEMM_BLOCKS    = (NN + 127) / 128;          // 782

    const float* hcur     = in_feat;
    float*       nexts[4] = { pA, pB, pA, out };

    for (int l = 0; l < 4; l++) {
        zero_kernel<<<ZERO_BLOCKS, 256>>>((float4*)pAgg);
        scatter_kernel<<<SCATTER_BLOCKS, 256>>>(hcur, src, dst, pAgg);
        const float* Wr = W_rel  + (size_t)l * DD * DD;
        const float* Wt = W_root + (size_t)l * DD * DD;
        const float* bb = b_rel  + (size_t)l * DD;
        if (l == 0)
            gemm_kernel<0><<<GEMM_BLOCKS, 256>>>(pAgg, hcur, Wr, Wt, bb, gamma, beta, nexts[l]);
        else if (l < 3)
            gemm_kernel<1><<<GEMM_BLOCKS, 256>>>(pAgg, hcur, Wr, Wt, bb, gamma, beta, nexts[l]);
        else
            gemm_kernel<2><<<GEMM_BLOCKS, 256>>>(pAgg, hcur, Wr, Wt, bb, gamma, beta, nexts[l]);
        hcur = nexts[l];
    }
}

// round 3
// speedup vs baseline: 1.6197x; 1.6197x over previous
#include <cuda_runtime.h>

#define NN 100000
#define DD 128
#define EE 1600000
#define SCAN_BLK 512
#define NSCAN ((NN + SCAN_BLK - 1) / SCAN_BLK)   // 196

// ---------------- scratch (no allocations allowed) ----------------
__device__ __align__(16) float g_bufA[NN * DD];
__device__ __align__(16) float g_bufB[NN * DD];
__device__ __align__(16) float g_agg [NN * DD];
__device__ int g_deg [NN];
__device__ int g_off [NN + 1];
__device__ int g_pos [NN];
__device__ int g_csrc[EE];
__device__ int g_bsum[NSCAN];

// ================= CSR build =================
__global__ void csr_zero(int* __restrict__ deg) {
    int i = blockIdx.x * blockDim.x + threadIdx.x;
    if (i < NN) deg[i] = 0;
}

__global__ void csr_count(const int* __restrict__ dst, int* __restrict__ deg) {
    int e = blockIdx.x * blockDim.x + threadIdx.x;
    if (e < EE) atomicAdd(deg + dst[e], 1);
}

// per-block exclusive scan (Hillis-Steele), block totals to bsum
__global__ void csr_scan1(const int* __restrict__ deg, int* __restrict__ off,
                          int* __restrict__ bsum) {
    __shared__ int sm[SCAN_BLK];
    int t = threadIdx.x;
    int i = blockIdx.x * SCAN_BLK + t;
    int v = (i < NN) ? deg[i] : 0;
    sm[t] = v;
    __syncthreads();
#pragma unroll
    for (int o = 1; o < SCAN_BLK; o <<= 1) {
        int add = (t >= o) ? sm[t - o] : 0;
        __syncthreads();
        sm[t] += add;
        __syncthreads();
    }
    if (i < NN) off[i] = sm[t] - v;           // exclusive within block
    if (t == SCAN_BLK - 1) bsum[blockIdx.x] = sm[t];
}

__global__ void csr_scan2(int* __restrict__ bsum, int* __restrict__ off) {
    if (threadIdx.x == 0) {
        int s = 0;
        for (int i = 0; i < NSCAN; i++) { int t = bsum[i]; bsum[i] = s; s += t; }
        off[NN] = s;   // == EE
    }
}

__global__ void csr_scan3(int* __restrict__ off, const int* __restrict__ bsum,
                          int* __restrict__ pos) {
    int i = blockIdx.x * blockDim.x + threadIdx.x;
    if (i < NN) {
        int o = off[i] + bsum[i / SCAN_BLK];
        off[i] = o;
        pos[i] = o;
    }
}

__global__ void csr_fill(const int* __restrict__ src, const int* __restrict__ dst,
                         int* __restrict__ pos, int* __restrict__ csrc) {
    int e = blockIdx.x * blockDim.x + threadIdx.x;
    if (e < EE) {
        int p = atomicAdd(pos + dst[e], 1);
        csrc[p] = src[e];
    }
}

// ================= aggregation: one warp per node, CSR gather =================
__global__ void __launch_bounds__(256)
gather_kernel(const float* __restrict__ h, const int* __restrict__ off,
              const int* __restrict__ csrc, float* __restrict__ agg) {
    int warp = (blockIdx.x * blockDim.x + threadIdx.x) >> 5;
    int lane = threadIdx.x & 31;
    if (warp >= NN) return;
    int s0 = __ldg(off + warp);
    int s1 = __ldg(off + warp + 1);
    const float4* hp = reinterpret_cast<const float4*>(h);
    float4 acc = make_float4(0.f, 0.f, 0.f, 0.f);
    int i = s0;
    for (; i + 4 <= s1; i += 4) {
        int a = __ldg(csrc + i);
        int b = __ldg(csrc + i + 1);
        int c = __ldg(csrc + i + 2);
        int d = __ldg(csrc + i + 3);
        float4 v0 = __ldg(hp + (size_t)a * 32 + lane);
        float4 v1 = __ldg(hp + (size_t)b * 32 + lane);
        float4 v2 = __ldg(hp + (size_t)c * 32 + lane);
        float4 v3 = __ldg(hp + (size_t)d * 32 + lane);
        acc.x += v0.x + v1.x + v2.x + v3.x;
        acc.y += v0.y + v1.y + v2.y + v3.y;
        acc.z += v0.z + v1.z + v2.z + v3.z;
        acc.w += v0.w + v1.w + v2.w + v3.w;
    }
    for (; i < s1; i++) {
        int a = __ldg(csrc + i);
        float4 v = __ldg(hp + (size_t)a * 32 + lane);
        acc.x += v.x; acc.y += v.y; acc.z += v.z; acc.w += v.w;
    }
    reinterpret_cast<float4*>(agg)[(size_t)warp * 32 + lane] = acc;
}

// ---------------- fused GEMM:  out = agg@Wrel + b + h@Wroot  (+epilogue) ----------------
// MODE 0: relu -> LN                 (input layer)
// MODE 1: +h residual -> relu -> LN  (middle layers)
// MODE 2: plain                      (output layer)
template <int MODE>
__global__ void __launch_bounds__(256, 2)
gemm_kernel(const float* __restrict__ agg,  const float* __restrict__ hin,
            const float* __restrict__ Wrel, const float* __restrict__ Wroot,
            const float* __restrict__ bias, const float* __restrict__ gamma,
            const float* __restrict__ beta, float* __restrict__ outp) {
    __shared__ float As[16][128];
    __shared__ float Ws[16][128];

    const int tid     = threadIdx.x;
    const int tx      = tid & 15;
    const int ty      = tid >> 4;
    const int rowBase = blockIdx.x * 128;

    float acc[8][8];
#pragma unroll
    for (int i = 0; i < 8; i++)
#pragma unroll
        for (int j = 0; j < 8; j++) acc[i][j] = 0.f;

    for (int kt = 0; kt < 16; kt++) {
        const int kk0 = kt * 16;
#pragma unroll
        for (int r = 0; r < 2; r++) {
            int f4   = tid + r * 256;
            int row  = f4 >> 2;
            int kq   = f4 & 3;
            int grow = rowBase + row;
            int kk   = kk0 + kq * 4;
            float4 v = make_float4(0.f, 0.f, 0.f, 0.f);
            if (grow < NN) {
                const float* b = (kk < DD)
                    ? (agg + (size_t)grow * DD + kk)
                    : (hin + (size_t)grow * DD + (kk - DD));
                v = *reinterpret_cast<const float4*>(b);
            }
            As[kq * 4 + 0][row] = v.x;
            As[kq * 4 + 1][row] = v.y;
            As[kq * 4 + 2][row] = v.z;
            As[kq * 4 + 3][row] = v.w;
        }
#pragma unroll
        for (int r = 0; r < 2; r++) {
            int f4 = tid + r * 256;
            int k  = f4 >> 5;
            int nq = f4 & 31;
            int kk = kk0 + k;
            const float* b = (kk < DD)
                ? (Wrel  + (size_t)kk * DD + nq * 4)
                : (Wroot + (size_t)(kk - DD) * DD + nq * 4);
            *reinterpret_cast<float4*>(&Ws[k][nq * 4]) =
                *reinterpret_cast<const float4*>(b);
        }
        __syncthreads();
#pragma unroll
        for (int k = 0; k < 16; k++) {
            float a[8], w[8];
            *reinterpret_cast<float4*>(&a[0]) = *reinterpret_cast<const float4*>(&As[k][ty * 4]);
            *reinterpret_cast<float4*>(&a[4]) = *reinterpret_cast<const float4*>(&As[k][64 + ty * 4]);
            *reinterpret_cast<float4*>(&w[0]) = *reinterpret_cast<const float4*>(&Ws[k][tx * 4]);
            *reinterpret_cast<float4*>(&w[4]) = *reinterpret_cast<const float4*>(&Ws[k][64 + tx * 4]);
#pragma unroll
            for (int i = 0; i < 8; i++)
#pragma unroll
                for (int j = 0; j < 8; j++)
                    acc[i][j] += a[i] * w[j];
        }
        __syncthreads();
    }

    float bb[8], gg[8], be[8];
    *reinterpret_cast<float4*>(&bb[0]) = *reinterpret_cast<const float4*>(bias + tx * 4);
    *reinterpret_cast<float4*>(&bb[4]) = *reinterpret_cast<const float4*>(bias + 64 + tx * 4);
    if (MODE != 2) {
        *reinterpret_cast<float4*>(&gg[0]) = *reinterpret_cast<const float4*>(gamma + tx * 4);
        *reinterpret_cast<float4*>(&gg[4]) = *reinterpret_cast<const float4*>(gamma + 64 + tx * 4);
        *reinterpret_cast<float4*>(&be[0]) = *reinterpret_cast<const float4*>(beta + tx * 4);
        *reinterpret_cast<float4*>(&be[4]) = *reinterpret_cast<const float4*>(beta + 64 + tx * 4);
    }

#pragma unroll
    for (int i = 0; i < 8; i++) {
        int  m     = rowBase + ((i < 4) ? (ty * 4 + i) : (64 + ty * 4 + (i - 4)));
        bool valid = (m < NN);
        float v[8];
        float res[8];
        if (MODE == 1) {
            if (valid) {
                *reinterpret_cast<float4*>(&res[0]) =
                    *reinterpret_cast<const float4*>(hin + (size_t)m * DD + tx * 4);
                *reinterpret_cast<float4*>(&res[4]) =
                    *reinterpret_cast<const float4*>(hin + (size_t)m * DD + 64 + tx * 4);
            } else {
#pragma unroll
                for (int j = 0; j < 8; j++) res[j] = 0.f;
            }
        }
#pragma unroll
        for (int j = 0; j < 8; j++) {
            float t = acc[i][j] + bb[j];
            if (MODE == 1) t += res[j];
            if (MODE != 2) t = fmaxf(t, 0.f);
            v[j] = t;
        }
        if (MODE == 2) {
            if (valid) {
                *reinterpret_cast<float4*>(outp + (size_t)m * DD + tx * 4) =
                    *reinterpret_cast<const float4*>(&v[0]);
                *reinterpret_cast<float4*>(outp + (size_t)m * DD + 64 + tx * 4) =
                    *reinterpret_cast<const float4*>(&v[4]);
            }
            continue;
        }
        float s = 0.f, q = 0.f;
#pragma unroll
        for (int j = 0; j < 8; j++) { s += v[j]; q += v[j] * v[j]; }
#pragma unroll
        for (int o = 1; o < 16; o <<= 1) {
            s += __shfl_xor_sync(0xffffffffu, s, o);
            q += __shfl_xor_sync(0xffffffffu, q, o);
        }
        float mean = s * (1.f / 128.f);
        float var  = q * (1.f / 128.f) - mean * mean;
        float rstd = rsqrtf(var + 1e-5f);
#pragma unroll
        for (int j = 0; j < 8; j++)
            v[j] = (v[j] - mean) * rstd * gg[j] + be[j];
        if (valid) {
            *reinterpret_cast<float4*>(outp + (size_t)m * DD + tx * 4) =
                *reinterpret_cast<const float4*>(&v[0]);
            *reinterpret_cast<float4*>(outp + (size_t)m * DD + 64 + tx * 4) =
                *reinterpret_cast<const float4*>(&v[4]);
        }
    }
}

// ---------------- driver ----------------
extern "C" void kernel_launch(void* const* d_in, const int* in_sizes, int n_in,
                              void* d_out, int out_size) {
    const float* in_feat = (const float*)d_in[0];
    const int*   ei      = (const int*)  d_in[1];   // [2, E]: src then dst
    const float* W_rel   = (const float*)d_in[2];
    const float* b_rel   = (const float*)d_in[3];
    const float* W_root  = (const float*)d_in[4];
    const float* gamma   = (const float*)d_in[5];
    const float* beta    = (const float*)d_in[6];
    float*       out     = (float*)d_out;

    float *pA = nullptr, *pB = nullptr, *pAgg = nullptr;
    int *pDeg, *pOff, *pPos, *pCsrc, *pBsum;
    cudaGetSymbolAddress((void**)&pA,    g_bufA);
    cudaGetSymbolAddress((void**)&pB,    g_bufB);
    cudaGetSymbolAddress((void**)&pAgg,  g_agg);
    cudaGetSymbolAddress((void**)&pDeg,  g_deg);
    cudaGetSymbolAddress((void**)&pOff,  g_off);
    cudaGetSymbolAddress((void**)&pPos,  g_pos);
    cudaGetSymbolAddress((void**)&pCsrc, g_csrc);
    cudaGetSymbolAddress((void**)&pBsum, g_bsum);

    const int* src = ei;
    const int* dst = ei + EE;

    // ---- CSR build (once per call; graph shared by all 4 layers) ----
    csr_zero <<<(NN + 255) / 256, 256>>>(pDeg);
    csr_count<<<(EE + 255) / 256, 256>>>(dst, pDeg);
    csr_scan1<<<NSCAN, SCAN_BLK>>>(pDeg, pOff, pBsum);
    csr_scan2<<<1, 32>>>(pBsum, pOff);
    csr_scan3<<<(NN + 255) / 256, 256>>>(pOff, pBsum, pPos);
    csr_fill <<<(EE + 255) / 256, 256>>>(src, dst, pPos, pCsrc);

    const int GATHER_BLOCKS = (NN * 32 + 255) / 256;   // 12500
    const int GEMM_BLOCKS   = (NN + 127) / 128;        // 782

    const float* hcur     = in_feat;
    float*       nexts[4] = { pA, pB, pA, out };

    for (int l = 0; l < 4; l++) {
        gather_kernel<<<GATHER_BLOCKS, 256>>>(hcur, pOff, pCsrc, pAgg);
        const float* Wr = W_rel  + (size_t)l * DD * DD;
        const float* Wt = W_root + (size_t)l * DD * DD;
        const float* bb = b_rel  + (size_t)l * DD;
        if (l == 0)
            gemm_kernel<0><<<GEMM_BLOCKS, 256>>>(pAgg, hcur, Wr, Wt, bb, gamma, beta, nexts[l]);
        else if (l < 3)
            gemm_kernel<1><<<GEMM_BLOCKS, 256>>>(pAgg, hcur, Wr, Wt, bb, gamma, beta, nexts[l]);
        else
            gemm_kernel<2><<<GEMM_BLOCKS, 256>>>(pAgg, hcur, Wr, Wt, bb, gamma, beta, nexts[l]);
        hcur = nexts[l];
    }
}